// round 3
// baseline (speedup 1.0000x reference)
#include <cuda_runtime.h>
#include <math.h>

#define BD 8
#define SD 128
#define ED 50
#define DD 300
#define DED 50
#define EPSV 1e-6f

#define NODE_ELEMS (BD*SD*DD)          // 307200
#define EDGE_ELEMS (BD*SD*SD*DED)      // 6553600

// ---- scratch (no allocation allowed) ----
__device__ float g_wsum[BD*SD*SD];     // 131072  collapsed adjacency
__device__ float g_y[BD*SD*DD];        // 307200  x @ W_w
__device__ float g_node[BD*SD*DD];     // 307200  relu(ln(...))
__device__ float g_tJ[BD*SD*DED];      // 51200   j-dependent refine term
__device__ float g_tI[BD*SD*DED];      // 51200   i-dependent refine term

// ============================================================
// k1: Wsum[b,i,j] = (1/E) * sum_e softmax[b,i,j,e] + (i==j)
// ============================================================
__global__ __launch_bounds__(256) void k_wsum(const float* __restrict__ wps) {
    __shared__ float tile[128 * ED];
    int rbase = blockIdx.x * 128;
    const float* src = wps + (size_t)rbase * ED;
    for (int t = threadIdx.x; t < 128 * ED; t += 256) tile[t] = src[t];
    __syncthreads();
    if (threadIdx.x < 128) {
        int r = threadIdx.x;
        float s = 0.f;
        #pragma unroll
        for (int e = 0; e < ED; e++) s += tile[r * ED + e];
        int row = rbase + r;
        int j = row & 127;
        int i = (row >> 7) & 127;
        g_wsum[row] = s * (1.0f / (float)ED) + (i == j ? 1.0f : 0.0f);
    }
}

// ============================================================
// k2a: y[gi, o] = sum_d x[gi, d] * W_w[d, o]   (gi = b*S+i, 1024 rows)
// ============================================================
__global__ __launch_bounds__(320) void k_xw(const float* __restrict__ x,
                                            const float* __restrict__ Ww) {
    __shared__ float xs[8 * DD];
    int rbase = blockIdx.x * 8;
    const float* src = x + (size_t)rbase * DD;
    for (int t = threadIdx.x; t < 8 * DD; t += 320) xs[t] = src[t];
    __syncthreads();
    int o = threadIdx.x;
    if (o >= DD) return;
    float acc[8];
    #pragma unroll
    for (int r = 0; r < 8; r++) acc[r] = 0.f;
    #pragma unroll 4
    for (int d = 0; d < DD; d++) {
        float w = Ww[d * DD + o];
        #pragma unroll
        for (int r = 0; r < 8; r++) acc[r] += xs[r * DD + d] * w;
    }
    #pragma unroll
    for (int r = 0; r < 8; r++) g_y[(size_t)(rbase + r) * DD + o] = acc[r];
}

// ============================================================
// k2b: h = Wsum @ y + W_b, then LayerNorm (unbiased std, +eps) + ReLU
//      8 rows per block, 320 threads (o < 300)
// ============================================================
__global__ __launch_bounds__(320) void k_gcn_ln(const float* __restrict__ Wb,
                                                const float* __restrict__ lna,
                                                const float* __restrict__ lnb,
                                                float* __restrict__ node_out) {
    __shared__ float wr[8 * SD];
    __shared__ float redA[10];
    __shared__ float redB[10];
    __shared__ float bc[2];
    int gibase = blockIdx.x * 8;         // rows gi = b*S+i
    int b = gibase >> 7;
    for (int t = threadIdx.x; t < 8 * SD; t += 320)
        wr[t] = g_wsum[(size_t)gibase * SD + t];
    __syncthreads();

    int o = threadIdx.x;
    float acc[8];
    #pragma unroll
    for (int r = 0; r < 8; r++) acc[r] = 0.f;
    if (o < DD) {
        const float* yb = g_y + (size_t)(b * SD) * DD + o;
        #pragma unroll 2
        for (int j = 0; j < SD; j++) {
            float v = yb[(size_t)j * DD];
            #pragma unroll
            for (int r = 0; r < 8; r++) acc[r] += wr[r * SD + j] * v;
        }
        float bias = Wb[o];
        #pragma unroll
        for (int r = 0; r < 8; r++) acc[r] += bias;
    }
    float la = (o < DD) ? lna[o] : 0.f;
    float lb = (o < DD) ? lnb[o] : 0.f;
    int lane = threadIdx.x & 31, wid = threadIdx.x >> 5;

    for (int r = 0; r < 8; r++) {
        float h = (o < DD) ? acc[r] : 0.f;
        float s1 = h, s2 = h * h;
        #pragma unroll
        for (int off = 16; off > 0; off >>= 1) {
            s1 += __shfl_down_sync(0xffffffffu, s1, off);
            s2 += __shfl_down_sync(0xffffffffu, s2, off);
        }
        if (lane == 0) { redA[wid] = s1; redB[wid] = s2; }
        __syncthreads();
        if (threadIdx.x == 0) {
            float t1 = 0.f, t2 = 0.f;
            #pragma unroll
            for (int w = 0; w < 10; w++) { t1 += redA[w]; t2 += redB[w]; }
            bc[0] = t1; bc[1] = t2;
        }
        __syncthreads();
        float mean = bc[0] * (1.0f / (float)DD);
        float var = (bc[1] - (float)DD * mean * mean) * (1.0f / (float)(DD - 1));
        var = fmaxf(var, 0.f);
        float inv = 1.0f / (sqrtf(var) + EPSV);
        if (o < DD) {
            float nv = la * (acc[r] - mean) * inv + lb;
            nv = fmaxf(nv, 0.f);
            size_t idx = (size_t)(gibase + r) * DD + o;
            g_node[idx] = nv;
            if (node_out) node_out[idx] = nv;
        }
        __syncthreads();   // protect bc/red before next row
    }
}

// ============================================================
// k3: per-(b,s) refine terms (rank-1-structured part of the big GEMM)
//   termJ[s,o] = diag[s]@rW[50:100] + node[s]@rW[150:450]
//   termI[s,o] = diag[s]@rW[100:150] + node[s]@rW[450:750]
//   16 rows/block, 256 threads: c=tid&63 (o, active<50), g=tid>>6 selects
//   (kind, row-half-of-8)
// ============================================================
__global__ __launch_bounds__(256) void k_terms(const float* __restrict__ wadj,
                                               const float* __restrict__ rW) {
    __shared__ float dg[16][ED];
    __shared__ float nd[16][DD];
    int gbase = blockIdx.x * 16;
    int b = gbase >> 7;
    for (int t = threadIdx.x; t < 16 * ED; t += 256) {
        int r = t / ED, e = t % ED;
        int s = (gbase + r) & 127;
        dg[r][e] = wadj[((size_t)(b * SD + s) * SD + s) * ED + e];
    }
    for (int t = threadIdx.x; t < 16 * DD; t += 256)
        nd[t / DD][t % DD] = g_node[(size_t)gbase * DD + t];
    __syncthreads();

    int c = threadIdx.x & 63;
    int g = threadIdx.x >> 6;
    if (c < DED) {
        bool kindJ = (g & 2) == 0;
        int rh = (g & 1) * 8;
        int offE = kindJ ? 50 : 100;
        int offD = kindJ ? 150 : 450;
        float acc[8];
        #pragma unroll
        for (int r = 0; r < 8; r++) acc[r] = 0.f;
        for (int e = 0; e < ED; e++) {
            float w = rW[(size_t)(offE + e) * DED + c];
            #pragma unroll
            for (int r = 0; r < 8; r++) acc[r] += dg[rh + r][e] * w;
        }
        for (int d = 0; d < DD; d++) {
            float w = rW[(size_t)(offD + d) * DED + c];
            #pragma unroll
            for (int r = 0; r < 8; r++) acc[r] += nd[rh + r][d] * w;
        }
        float* dst = kindJ ? g_tJ : g_tI;
        #pragma unroll
        for (int r = 0; r < 8; r++)
            dst[(size_t)(gbase + rh + r) * DED + c] = acc[r];
    }
}

// ============================================================
// k4: edge_out[row, o] = adj[row,:50] @ Wa + termJ[b,j] + termI[b,i] + rb
//   64 rows/block (same b,i), 256 threads: og=tid&3 -> 16 o's, r=tid>>2
// ============================================================
__global__ __launch_bounds__(256) void k_edge(const float* __restrict__ wadj,
                                              const float* __restrict__ rW,
                                              const float* __restrict__ rb,
                                              float* __restrict__ eout) {
    __shared__ __align__(16) float adjS[64 * ED];
    __shared__ __align__(16) float WaS[ED * 64];
    __shared__ float tJS[64 * DED];
    __shared__ float cI[64];
    int rbase = blockIdx.x * 64;
    int b = rbase >> 14;
    int i = (rbase >> 7) & 127;
    int jbase = rbase & 127;

    for (int t = threadIdx.x; t < 64 * ED; t += 256)
        adjS[t] = wadj[(size_t)rbase * ED + t];
    for (int t = threadIdx.x; t < ED * 64; t += 256) {
        int e = t >> 6, o = t & 63;
        WaS[t] = (o < DED) ? rW[(size_t)e * DED + o] : 0.f;
    }
    for (int t = threadIdx.x; t < 64 * DED; t += 256)
        tJS[t] = g_tJ[(size_t)(b * SD + jbase) * DED + t];
    if (threadIdx.x < 64) {
        int o = threadIdx.x;
        cI[o] = (o < DED) ? (g_tI[(size_t)(b * SD + i) * DED + o] + rb[o]) : 0.f;
    }
    __syncthreads();

    int og = threadIdx.x & 3;
    int r = threadIdx.x >> 2;
    float acc[16];
    #pragma unroll
    for (int k = 0; k < 16; k++) acc[k] = 0.f;
    const float* arow = adjS + r * ED;
    const float4* wbase = (const float4*)(WaS);   // 16 float4 per e-row
    int wcol = og * 4;                            // float4 index within e-row
    #pragma unroll 10
    for (int e = 0; e < ED; e++) {
        float a = arow[e];
        const float4* wp = wbase + e * 16 + wcol;
        float4 w0 = wp[0], w1 = wp[1], w2 = wp[2], w3 = wp[3];
        acc[0]  += a * w0.x;  acc[1]  += a * w0.y;  acc[2]  += a * w0.z;  acc[3]  += a * w0.w;
        acc[4]  += a * w1.x;  acc[5]  += a * w1.y;  acc[6]  += a * w1.z;  acc[7]  += a * w1.w;
        acc[8]  += a * w2.x;  acc[9]  += a * w2.y;  acc[10] += a * w2.z;  acc[11] += a * w2.w;
        acc[12] += a * w3.x;  acc[13] += a * w3.y;  acc[14] += a * w3.z;  acc[15] += a * w3.w;
    }
    int obase = og * 16;
    float* orow = eout + (size_t)(rbase + r) * DED;
    const float* tjr = tJS + r * DED;
    #pragma unroll
    for (int k = 0; k < 16; k++) {
        int o = obase + k;
        if (o < DED) orow[o] = acc[k] + tjr[o] + cI[o];
    }
}

// ============================================================
extern "C" void kernel_launch(void* const* d_in, const int* in_sizes, int n_in,
                              void* d_out, int out_size) {
    const float* wps  = (const float*)d_in[0];   // [B,S,S,E]
    const float* wadj = (const float*)d_in[1];   // [B,S,S,E]
    const float* x    = (const float*)d_in[2];   // [B,S,D]
    // d_in[3] self_loop: identity by construction -> unused
    const float* Ww   = (const float*)d_in[4];   // [D,D]
    const float* Wb   = (const float*)d_in[5];   // [D]
    const float* lna  = (const float*)d_in[6];   // [D]
    const float* lnb  = (const float*)d_in[7];   // [D]
    const float* rW   = (const float*)d_in[8];   // [750,50]
    const float* rb   = (const float*)d_in[9];   // [50]

    float* out = (float*)d_out;
    // Expected layout: node (307200) then edge_out (6553600).
    float* node_out = nullptr;
    float* edge_out;
    if (out_size >= NODE_ELEMS + EDGE_ELEMS) {
        node_out = out;
        edge_out = out + NODE_ELEMS;
    } else {
        edge_out = out + (out_size - EDGE_ELEMS);  // edge-only fallback
    }

    k_wsum  <<<BD*SD*SD/128, 256>>>(wps);
    k_xw    <<<BD*SD/8, 320>>>(x, Ww);
    k_gcn_ln<<<BD*SD/8, 320>>>(Wb, lna, lnb, node_out);
    k_terms <<<BD*SD/16, 256>>>(wadj, rW);
    k_edge  <<<BD*SD*SD/64, 256>>>(wadj, rW, rb, edge_out);
}

// round 6
// speedup vs baseline: 1.7943x; 1.7943x over previous
#include <cuda_runtime.h>
#include <math.h>

#define BD 8
#define SD 128
#define ED 50
#define DD 300
#define DED 50
#define EPSV 1e-6f

#define NODE_ELEMS (BD*SD*DD)          // 307200
#define EDGE_ELEMS (BD*SD*SD*DED)      // 6553600

// ---- scratch (no allocation allowed) ----
__device__ float g_wsum[BD*SD*SD];     // 131072  collapsed adjacency
__device__ float g_y[BD*SD*DD];        // 307200  x @ W_w
__device__ float g_node[BD*SD*DD];     // 307200  relu(ln(...))
__device__ float g_tJ[BD*SD*DED];      // 51200   j-dependent refine term
__device__ float g_tI[BD*SD*DED];      // 51200   i-dependent refine term

// ============================================================
// k1: Wsum[b,i,j] = (1/E) * sum_e softmax[b,i,j,e] + (i==j)
// ============================================================
__global__ __launch_bounds__(256) void k_wsum(const float* __restrict__ wps) {
    __shared__ float tile[128 * ED];
    int rbase = blockIdx.x * 128;
    const float* src = wps + (size_t)rbase * ED;
    for (int t = threadIdx.x; t < 128 * ED; t += 256) tile[t] = src[t];
    __syncthreads();
    if (threadIdx.x < 128) {
        int r = threadIdx.x;
        float s = 0.f;
        #pragma unroll
        for (int e = 0; e < ED; e++) s += tile[r * ED + e];
        int row = rbase + r;
        int j = row & 127;
        int i = (row >> 7) & 127;
        g_wsum[row] = s * (1.0f / (float)ED) + (i == j ? 1.0f : 0.0f);
    }
}

// ============================================================
// k2a: y[gi, o] = sum_d x[gi, d] * W_w[d, o]   (4 rows/block, grid=256)
// ============================================================
__global__ __launch_bounds__(320) void k_xw(const float* __restrict__ x,
                                            const float* __restrict__ Ww) {
    __shared__ float xs[4 * DD];
    int rbase = blockIdx.x * 4;
    const float* src = x + (size_t)rbase * DD;
    for (int t = threadIdx.x; t < 4 * DD; t += 320) xs[t] = src[t];
    __syncthreads();
    int o = threadIdx.x;
    if (o >= DD) return;
    float a0 = 0.f, a1 = 0.f, a2 = 0.f, a3 = 0.f;
    #pragma unroll 5
    for (int d = 0; d < DD; d++) {
        float w = Ww[d * DD + o];
        a0 += xs[d] * w;
        a1 += xs[DD + d] * w;
        a2 += xs[2 * DD + d] * w;
        a3 += xs[3 * DD + d] * w;
    }
    g_y[(size_t)rbase * DD + o] = a0;
    g_y[(size_t)(rbase + 1) * DD + o] = a1;
    g_y[(size_t)(rbase + 2) * DD + o] = a2;
    g_y[(size_t)(rbase + 3) * DD + o] = a3;
}

// ============================================================
// k2b: h = Wsum @ y + W_b, then LayerNorm (unbiased std +eps) + ReLU
//      4 rows/block, grid=256, 320 threads
// ============================================================
__global__ __launch_bounds__(320) void k_gcn_ln(const float* __restrict__ Wb,
                                                const float* __restrict__ lna,
                                                const float* __restrict__ lnb,
                                                float* __restrict__ node_out) {
    __shared__ float wr[4 * SD];
    __shared__ float redA[10];
    __shared__ float redB[10];
    __shared__ float bc[2];
    int gibase = blockIdx.x * 4;         // rows gi = b*S+i
    int b = gibase >> 7;
    for (int t = threadIdx.x; t < 4 * SD; t += 320)
        wr[t] = g_wsum[(size_t)gibase * SD + t];
    __syncthreads();

    int o = threadIdx.x;
    float acc[4];
    #pragma unroll
    for (int r = 0; r < 4; r++) acc[r] = 0.f;
    if (o < DD) {
        const float* yb = g_y + (size_t)(b * SD) * DD + o;
        #pragma unroll 4
        for (int j = 0; j < SD; j++) {
            float v = yb[(size_t)j * DD];
            #pragma unroll
            for (int r = 0; r < 4; r++) acc[r] += wr[r * SD + j] * v;
        }
        float bias = Wb[o];
        #pragma unroll
        for (int r = 0; r < 4; r++) acc[r] += bias;
    }
    float la = (o < DD) ? lna[o] : 0.f;
    float lb = (o < DD) ? lnb[o] : 0.f;
    int lane = threadIdx.x & 31, wid = threadIdx.x >> 5;

    for (int r = 0; r < 4; r++) {
        float h = (o < DD) ? acc[r] : 0.f;
        float s1 = h, s2 = h * h;
        #pragma unroll
        for (int off = 16; off > 0; off >>= 1) {
            s1 += __shfl_down_sync(0xffffffffu, s1, off);
            s2 += __shfl_down_sync(0xffffffffu, s2, off);
        }
        if (lane == 0) { redA[wid] = s1; redB[wid] = s2; }
        __syncthreads();
        if (threadIdx.x == 0) {
            float t1 = 0.f, t2 = 0.f;
            #pragma unroll
            for (int w = 0; w < 10; w++) { t1 += redA[w]; t2 += redB[w]; }
            bc[0] = t1; bc[1] = t2;
        }
        __syncthreads();
        float mean = bc[0] * (1.0f / (float)DD);
        float var = (bc[1] - (float)DD * mean * mean) * (1.0f / (float)(DD - 1));
        var = fmaxf(var, 0.f);
        float inv = 1.0f / (sqrtf(var) + EPSV);
        if (o < DD) {
            float nv = la * (acc[r] - mean) * inv + lb;
            nv = fmaxf(nv, 0.f);
            size_t idx = (size_t)(gibase + r) * DD + o;
            g_node[idx] = nv;
            if (node_out) node_out[idx] = nv;
        }
        __syncthreads();   // protect bc/red before next row
    }
}

// ============================================================
// k3: per-(b,s) refine terms.  block = (kind, 4 rows), grid = 512.
//   termJ[s,o] = diag[s]@rW[50:100]  + node[s]@rW[150:450]
//   termI[s,o] = diag[s]@rW[100:150] + node[s]@rW[450:750]
//   256 thr: c = tid&63 (o, active<50), rq = tid>>6 -> row within group
// ============================================================
__global__ __launch_bounds__(256) void k_terms(const float* __restrict__ wadj,
                                               const float* __restrict__ rW) {
    __shared__ float dg[4][ED];
    __shared__ float nd[4][DD];
    int kind = blockIdx.x & 1;           // 0 = J, 1 = I
    int gbase = (blockIdx.x >> 1) * 4;
    int b = gbase >> 7;
    for (int t = threadIdx.x; t < 4 * ED; t += 256) {
        int r = t / ED, e = t % ED;
        int s = (gbase + r) & 127;
        dg[r][e] = wadj[((size_t)(b * SD + s) * SD + s) * ED + e];
    }
    for (int t = threadIdx.x; t < 4 * DD; t += 256)
        nd[t / DD][t % DD] = g_node[(size_t)gbase * DD + t];
    __syncthreads();

    int c = threadIdx.x & 63;
    int rq = threadIdx.x >> 6;
    if (c >= DED) return;
    int offE = kind ? 100 : 50;
    int offD = kind ? 450 : 150;
    float acc = 0.f;
    #pragma unroll 10
    for (int e = 0; e < ED; e++)
        acc += dg[rq][e] * __ldg(&rW[(size_t)(offE + e) * DED + c]);
    #pragma unroll 10
    for (int d = 0; d < DD; d++)
        acc += nd[rq][d] * __ldg(&rW[(size_t)(offD + d) * DED + c]);
    float* dst = kind ? g_tI : g_tJ;
    dst[(size_t)(gbase + rq) * DED + c] = acc;
}

// ============================================================
// k4: edge_out[row,o] = adj[row,:50] @ Wa + termJ[b,j] + termI[b,i] + rb
//   Tile: 64 rows x 64 cols (50 valid), 128 threads, each thread 4x8.
//   grid = 16384/64 = 256 blocks; 64 rows share (b,i), span j.
// ============================================================
__global__ __launch_bounds__(128) void k_edge(const float* __restrict__ wadj,
                                              const float* __restrict__ rW,
                                              const float* __restrict__ rb,
                                              float* __restrict__ eout) {
    __shared__ float adjS[64][52];                 // padded to break conflicts
    __shared__ __align__(16) float WaS[ED][64];    // [e][o], o padded to 64
    __shared__ float tJS[64][DED];
    __shared__ float cI[64];
    int rbase = blockIdx.x * 64;
    int b = rbase >> 14;
    int i = (rbase >> 7) & 127;
    int jbase = rbase & 127;

    for (int t = threadIdx.x; t < 64 * ED; t += 128) {
        int r = t / ED, e = t % ED;
        adjS[r][e] = wadj[(size_t)rbase * ED + t];
    }
    for (int t = threadIdx.x; t < ED * 64; t += 128) {
        int e = t >> 6, o = t & 63;
        WaS[e][o] = (o < DED) ? rW[(size_t)e * DED + o] : 0.f;
    }
    for (int t = threadIdx.x; t < 64 * DED; t += 128)
        tJS[t / DED][t % DED] = g_tJ[(size_t)(b * SD + jbase) * DED + t];
    if (threadIdx.x < 64) {
        int o = threadIdx.x;
        cI[o] = (o < DED) ? (g_tI[(size_t)(b * SD + i) * DED + o] + rb[o]) : 0.f;
    }
    __syncthreads();

    int cg = threadIdx.x & 7;     // col group: cols cg*8 .. cg*8+7
    int rg = threadIdx.x >> 3;    // row group: rows rg*4 .. rg*4+3
    int r0 = rg * 4;
    int c0 = cg * 8;

    float acc[4][8];
    #pragma unroll
    for (int r = 0; r < 4; r++)
        #pragma unroll
        for (int k = 0; k < 8; k++) acc[r][k] = 0.f;

    #pragma unroll 2
    for (int e = 0; e < ED; e++) {
        float a[4];
        #pragma unroll
        for (int r = 0; r < 4; r++) a[r] = adjS[r0 + r][e];
        float4 w0 = *(const float4*)&WaS[e][c0];
        float4 w1 = *(const float4*)&WaS[e][c0 + 4];
        float w[8] = {w0.x, w0.y, w0.z, w0.w, w1.x, w1.y, w1.z, w1.w};
        #pragma unroll
        for (int r = 0; r < 4; r++)
            #pragma unroll
            for (int k = 0; k < 8; k++) acc[r][k] += a[r] * w[k];
    }

    #pragma unroll
    for (int r = 0; r < 4; r++) {
        int row = rbase + r0 + r;
        float* orow = eout + (size_t)row * DED;
        const float* tjr = tJS[r0 + r];
        #pragma unroll
        for (int k = 0; k < 8; k++) {
            int o = c0 + k;
            if (o < DED) orow[o] = acc[r][k] + tjr[o] + cI[o];
        }
    }
}

// ============================================================
extern "C" void kernel_launch(void* const* d_in, const int* in_sizes, int n_in,
                              void* d_out, int out_size) {
    const float* wps  = (const float*)d_in[0];   // [B,S,S,E]
    const float* wadj = (const float*)d_in[1];   // [B,S,S,E]
    const float* x    = (const float*)d_in[2];   // [B,S,D]
    // d_in[3] self_loop: identity by construction -> unused
    const float* Ww   = (const float*)d_in[4];   // [D,D]
    const float* Wb   = (const float*)d_in[5];   // [D]
    const float* lna  = (const float*)d_in[6];   // [D]
    const float* lnb  = (const float*)d_in[7];   // [D]
    const float* rW   = (const float*)d_in[8];   // [750,50]
    const float* rb   = (const float*)d_in[9];   // [50]

    float* out = (float*)d_out;
    float* node_out = nullptr;
    float* edge_out;
    if (out_size >= NODE_ELEMS + EDGE_ELEMS) {
        node_out = out;
        edge_out = out + NODE_ELEMS;
    } else {
        edge_out = out + (out_size - EDGE_ELEMS);  // edge-only fallback
    }

    k_wsum  <<<BD*SD*SD/128, 256>>>(wps);
    k_xw    <<<BD*SD/4, 320>>>(x, Ww);
    k_gcn_ln<<<BD*SD/4, 320>>>(Wb, lna, lnb, node_out);
    k_terms <<<2*BD*SD/4, 256>>>(wadj, rW);
    k_edge  <<<BD*SD*SD/64, 128>>>(wadj, rW, rb, edge_out);
}